// round 9
// baseline (speedup 1.0000x reference)
#include <cuda_runtime.h>
#include <cstdint>

#define T_STEPS 512
#define BATCH   512
#define HID     128
#define ACT     18
#define TBROWS  (T_STEPS * BATCH)   // 262144

// Scratch (device globals: allocation is forbidden)
__device__ float g_ys[(size_t)TBROWS * HID];         // emb, then ys (reused)
__device__ float g_gi [(size_t)TBROWS * 3 * HID];    // gi

typedef unsigned long long u64;

__device__ __forceinline__ u64 pk2(float x) {
    u64 d; asm("mov.b64 %0, {%1,%1};" : "=l"(d) : "f"(x)); return d;
}
__device__ __forceinline__ u64 pk2two(float a, float b) {
    u64 d; asm("mov.b64 %0, {%1,%2};" : "=l"(d) : "f"(a), "f"(b)); return d;
}
__device__ __forceinline__ void fma2(u64 &c, u64 a, u64 b) {
    asm("fma.rn.f32x2 %0, %1, %2, %3;" : "=l"(c) : "l"(a), "l"(b), "l"(c));
}
__device__ __forceinline__ float2 unpk(u64 v) {
    float2 f; asm("mov.b64 {%0,%1}, %2;" : "=f"(f.x), "=f"(f.y) : "l"(v)); return f;
}
__device__ __forceinline__ void cp_async16(uint32_t dst, const void* src) {
    asm volatile("cp.async.ca.shared.global [%0], [%1], 16;" :: "r"(dst), "l"(src));
}

// ---------------------------------------------------------------------------
// GEMM: C[M,N] = act(A[M,128] @ W[128,N] + bias[N]).
// CTA tile 64x128, 128 threads, thread tile 8x8, f32x2 accumulators.
// ---------------------------------------------------------------------------
template<bool RELU>
__global__ __launch_bounds__(128, 2) void gemm8x8(
    const float* __restrict__ A, const float* __restrict__ W,
    const float* __restrict__ bias, float* __restrict__ C, int N)
{
    extern __shared__ float sm[];
    float* As = sm;             // [64][132]
    float* Bs = sm + 64 * 132;  // [128][128]

    const int m0  = blockIdx.x * 64;
    const int n0  = blockIdx.y * 128;
    const int tid = threadIdx.x;

    for (int i = tid; i < 2048; i += 128) {
        int m = i >> 5, kv = (i & 31) << 2;
        *(float4*)(As + m * 132 + kv) =
            *(const float4*)(A + (size_t)(m0 + m) * 128 + kv);
    }
    for (int i = tid; i < 4096; i += 128) {
        int k = i >> 5, nv = (i & 31) << 2;
        *(float4*)(Bs + k * 128 + nv) =
            *(const float4*)(W + (size_t)k * N + n0 + nv);
    }
    __syncthreads();

    const int tx = tid & 15;
    const int ty = tid >> 4;

    u64 acc[8][4];
    #pragma unroll
    for (int r = 0; r < 8; ++r)
        #pragma unroll
        for (int c = 0; c < 4; ++c) acc[r][c] = 0ull;

    const float* ap = As + ty * 8 * 132;
    const u64*   bp = (const u64*)Bs + tx * 4;   // row stride 64 u64

    #pragma unroll
    for (int k4 = 0; k4 < 128; k4 += 4) {
        float4 av[8];
        #pragma unroll
        for (int r = 0; r < 8; ++r)
            av[r] = *(const float4*)(ap + r * 132 + k4);
        #pragma unroll
        for (int kk = 0; kk < 4; ++kk) {
            ulonglong2 b01 = *(const ulonglong2*)(bp + (size_t)(k4 + kk) * 64);
            ulonglong2 b23 = *(const ulonglong2*)(bp + (size_t)(k4 + kk) * 64 + 2);
            #pragma unroll
            for (int r = 0; r < 8; ++r) {
                u64 ad = pk2(((const float*)&av[r])[kk]);
                fma2(acc[r][0], ad, b01.x);
                fma2(acc[r][1], ad, b01.y);
                fma2(acc[r][2], ad, b23.x);
                fma2(acc[r][3], ad, b23.y);
            }
        }
    }

    float bb[8];
    {
        float4 b0 = *(const float4*)(bias + n0 + tx * 8);
        float4 b1 = *(const float4*)(bias + n0 + tx * 8 + 4);
        bb[0]=b0.x; bb[1]=b0.y; bb[2]=b0.z; bb[3]=b0.w;
        bb[4]=b1.x; bb[5]=b1.y; bb[6]=b1.z; bb[7]=b1.w;
    }
    #pragma unroll
    for (int r = 0; r < 8; ++r) {
        float2 f0 = unpk(acc[r][0]), f1 = unpk(acc[r][1]);
        float2 f2 = unpk(acc[r][2]), f3 = unpk(acc[r][3]);
        float v[8] = { f0.x, f0.y, f1.x, f1.y, f2.x, f2.y, f3.x, f3.y };
        #pragma unroll
        for (int j = 0; j < 8; ++j) {
            v[j] += bb[j];
            if (RELU) v[j] = fmaxf(v[j], 0.0f);
        }
        float* cp = C + (size_t)(m0 + ty * 8 + r) * N + n0 + tx * 8;
        *(float4*)(cp)     = make_float4(v[0], v[1], v[2], v[3]);
        *(float4*)(cp + 4) = make_float4(v[4], v[5], v[6], v[7]);
    }
}

// ---------------------------------------------------------------------------
// Scan: 128 CTAs x 384 threads, 4 batch rows per CTA.
// Hybrid Wh: k[0,64) in registers (w[64]), k[64,128) in smem TRANSPOSED
// (w_s[col][k], pitch 68 floats = 272B -> 16B-aligned LDS.128, phase
// conflict-free). Register slack lets ptxas pipeline the broadcast h4 LDS.
// ---------------------------------------------------------------------------
__device__ __forceinline__ float sigf(float x) {
    return __fdividef(1.0f, 1.0f + __expf(-x));
}
__device__ __forceinline__ float tanhfast(float x) {
    return __fdividef(2.0f, 1.0f + __expf(-2.0f * x)) - 1.0f;
}

// smem float offsets (keep 16B alignment where wide accesses occur)
#define SC_W     0                   // w_s[384][68] = 26112 floats
#define SC_H4    26112               // float4 h4_s[128]   (26112*4 % 16 == 0)
#define SC_GH01  26624               // u64 [384] -> 768 floats
#define SC_GH23  27392               // u64 [384] -> 768 floats
#define SC_BHN   28160               // float [128]
#define SC_MASK  28288               // float [2048]
#define SC_GI    30336               // float [2][1536]    (30336*4 % 16 == 0)
#define SC_TOTAL 33408               // floats -> 133632 bytes

__global__ __launch_bounds__(384, 1) void scan_kernel(
    const float* __restrict__ hidden, const float* __restrict__ gi_all,
    const int* __restrict__ dones,
    const float* __restrict__ Wh, const float* __restrict__ bhn,
    float* __restrict__ hfinal, float* __restrict__ ys)
{
    extern __shared__ float sm[];
    float*  w_s    = sm + SC_W;
    float4* h4_s   = (float4*)(sm + SC_H4);
    u64*    gh01_s = (u64*)(sm + SC_GH01);
    u64*    gh23_s = (u64*)(sm + SC_GH23);
    float*  bhn_s  = sm + SC_BHN;
    float*  maskf_s= sm + SC_MASK;
    float*  gi_s   = sm + SC_GI;

    const int tid = threadIdx.x;
    const int b0  = blockIdx.x * 4;

    const uint32_t gi_smem = (uint32_t)__cvta_generic_to_shared(gi_s)
                             + (uint32_t)tid * 16u;
    const float* gi_src = gi_all + (size_t)b0 * 384 + tid * 4;

    // Kick off gi for t=0 immediately
    cp_async16(gi_smem, gi_src);
    asm volatile("cp.async.commit_group;");

    // Wh k[0,64) column tid -> registers (coalesced LDG)
    float w[64];
    #pragma unroll
    for (int k = 0; k < 64; ++k)
        w[k] = Wh[(size_t)k * 384 + tid];

    // Wh k[64,128) -> smem transposed: w_s[col*68 + kk]
    for (int i = tid; i < 24576; i += 384) {
        int kk = i / 384, col = i % 384;            // src row 64+kk (coalesced in col)
        w_s[col * 68 + kk] = Wh[(size_t)(64 + kk) * 384 + col];
    }

    if (tid < 128) bhn_s[tid] = bhn[tid];
    for (int i = tid; i < T_STEPS * 4; i += 384) {
        int t = i >> 2, r = i & 3;
        maskf_s[i] = dones[t * BATCH + b0 + r] ? 0.0f : 1.0f;
    }
    for (int idx = tid; idx < 512; idx += 384) {
        int r = idx >> 7, i = idx & 127;
        ((float*)&h4_s[i])[r] = hidden[(size_t)(b0 + r) * 128 + i];
    }
    __syncthreads();

    const int rr0 = tid >> 7;
    const int i0  = tid & 127;
    const float* wsp = w_s + tid * 68;

    for (int t = 0; t < T_STEPS; ++t) {
        // issue cp.async for t+1 (lands during the matvec)
        if (t + 1 < T_STEPS) {
            cp_async16(gi_smem + (((t + 1) & 1) ? 6144u : 0u),
                       gi_src + (size_t)(t + 1) * (BATCH * 384));
            asm volatile("cp.async.commit_group;");
        }

        // matvec: gh[:, tid] = h4 . Wh[:, tid]
        u64 a01 = 0ull, a23 = 0ull;
        // k in [0,64): w from registers
        #pragma unroll
        for (int k = 0; k < 64; ++k) {
            ulonglong2 hv = *(const ulonglong2*)&h4_s[k];
            u64 wd = pk2(w[k]);
            fma2(a01, hv.x, wd);
            fma2(a23, hv.y, wd);
        }
        // k in [64,128): w from smem, 4 at a time (LDS.128, 16B-aligned)
        #pragma unroll
        for (int k4 = 0; k4 < 16; ++k4) {
            float4 wv = *(const float4*)(wsp + k4 * 4);
            #pragma unroll
            for (int kk = 0; kk < 4; ++kk) {
                ulonglong2 hv = *(const ulonglong2*)&h4_s[64 + k4 * 4 + kk];
                u64 wd = pk2(((const float*)&wv)[kk]);
                fma2(a01, hv.x, wd);
                fma2(a23, hv.y, wd);
            }
        }
        gh01_s[tid] = a01;
        gh23_s[tid] = a23;

        if (t + 1 < T_STEPS) {
            asm volatile("cp.async.wait_group 1;");   // gi[t] landed
        } else {
            asm volatile("cp.async.wait_group 0;");
        }
        __syncthreads();   // (A) gh + gi[t] visible; matvec reads of h4 done

        const float* gbuf = gi_s + (t & 1) * 1536;

        // gates slot 0: item (rr0, i0)
        {
            const float mk = maskf_s[t * 4 + rr0];
            const float* gb = gbuf + rr0 * 384;
            const float* g = (rr0 < 2) ? (const float*)gh01_s : (const float*)gh23_s;
            const int sub = rr0 & 1;
            float ghr = g[2 * i0 + sub];
            float ghz = g[2 * (128 + i0) + sub];
            float ghn = g[2 * (256 + i0) + sub];
            float rg = sigf(gb[i0] + mk * ghr);
            float zg = sigf(gb[128 + i0] + mk * ghz);
            float nv = tanhfast(gb[256 + i0] + rg * (mk * ghn + bhn_s[i0]));
            float* hp = ((float*)&h4_s[i0]) + rr0;
            float hn = (1.0f - zg) * nv + zg * (*hp * mk);
            *hp = hn;
            ys[((size_t)t * BATCH + b0 + rr0) * 128 + i0] = hn;
        }
        // gates slot 1: row 3
        if (tid < 128) {
            const float mk = maskf_s[t * 4 + 3];
            const float* gb = gbuf + 3 * 384;
            const float* g = (const float*)gh23_s;
            float ghr = g[2 * tid + 1];
            float ghz = g[2 * (128 + tid) + 1];
            float ghn = g[2 * (256 + tid) + 1];
            float rg = sigf(gb[tid] + mk * ghr);
            float zg = sigf(gb[128 + tid] + mk * ghz);
            float nv = tanhfast(gb[256 + tid] + rg * (mk * ghn + bhn_s[tid]));
            float* hp = ((float*)&h4_s[tid]) + 3;
            float hn = (1.0f - zg) * nv + zg * (*hp * mk);
            *hp = hn;
            ys[((size_t)t * BATCH + b0 + 3) * 128 + tid] = hn;
        }
        __syncthreads();   // (B) h4 updated before next matvec
    }

    for (int idx = tid; idx < 512; idx += 384) {
        int r = idx >> 7, i = idx & 127;
        hfinal[(size_t)(b0 + r) * 128 + i] = ((float*)&h4_s[i])[r];
    }
}

// ---------------------------------------------------------------------------
// q projection: q[M,18] = ys[M,128] @ W_out[128,18] + b_out.
// 128 rows/CTA, 128 threads (1 row/thread), 2 CTAs/SM.
// ---------------------------------------------------------------------------
__global__ __launch_bounds__(128, 2) void qproj_kernel(
    const float* __restrict__ ys, const float* __restrict__ Wo,
    const float* __restrict__ bo, float* __restrict__ q)
{
    extern __shared__ float sm[];
    float* As   = sm;                 // [128][129]
    float* Wo_s = sm + 128 * 129;     // [128][20]
    float* bo_s = Wo_s + 128 * 20;    // [18]

    const int tid = threadIdx.x;
    const size_t m0 = (size_t)blockIdx.x * 128;

    for (int i = tid; i < 4096; i += 128) {
        int m = i >> 5, kv = (i & 31) << 2;
        float4 v = *(const float4*)(ys + (m0 + m) * 128 + kv);
        float* d = As + m * 129 + kv;
        d[0] = v.x; d[1] = v.y; d[2] = v.z; d[3] = v.w;
    }
    for (int i = tid; i < 128 * 18; i += 128)
        Wo_s[(i / 18) * 20 + (i % 18)] = Wo[i];
    if (tid < 18) bo_s[tid] = bo[tid];
    __syncthreads();

    u64 acc[9];
    #pragma unroll
    for (int p = 0; p < 9; ++p) acc[p] = pk2two(bo_s[2 * p], bo_s[2 * p + 1]);

    const float* ap = As + tid * 129;
    #pragma unroll 4
    for (int k = 0; k < 128; ++k) {
        u64 hd = pk2(ap[k]);
        const u64* wrow = (const u64*)(Wo_s + k * 20);
        #pragma unroll
        for (int p = 0; p < 9; ++p) fma2(acc[p], hd, wrow[p]);
    }

    float* qp = q + (m0 + tid) * ACT;
    #pragma unroll
    for (int p = 0; p < 9; ++p) {
        float2 f = unpk(acc[p]);
        *(float2*)(qp + 2 * p) = f;
    }
}

// ---------------------------------------------------------------------------
extern "C" void kernel_launch(void* const* d_in, const int* in_sizes, int n_in,
                              void* d_out, int out_size)
{
    const float* hidden = (const float*)d_in[0];
    const float* obs    = (const float*)d_in[1];
    const int*   dones  = (const int*)d_in[2];
    const float* W_emb  = (const float*)d_in[3];
    const float* b_emb  = (const float*)d_in[4];
    const float* Wi     = (const float*)d_in[5];
    const float* bi     = (const float*)d_in[6];
    const float* Wh     = (const float*)d_in[7];
    const float* bhn    = (const float*)d_in[8];
    const float* W_out  = (const float*)d_in[9];
    const float* b_out  = (const float*)d_in[10];

    float* out    = (float*)d_out;
    float* hfinal = out;                        // [512, 128]
    float* q      = out + (size_t)BATCH * HID;  // [512, 512, 18]

    void *p_ys, *p_gi;
    cudaGetSymbolAddress(&p_ys, g_ys);
    cudaGetSymbolAddress(&p_gi, g_gi);
    float* embys = (float*)p_ys;   // emb, later ys
    float* gi    = (float*)p_gi;

    const int gemm_smem  = (64 * 132 + 128 * 128) * 4;       // 99328 B
    const int scan_smem  = SC_TOTAL * 4;                     // 133632 B
    const int qproj_smem = (128 * 129 + 128 * 20 + 18) * 4;  // 76360 B
    cudaFuncSetAttribute(gemm8x8<true>,
        cudaFuncAttributeMaxDynamicSharedMemorySize, gemm_smem);
    cudaFuncSetAttribute(gemm8x8<false>,
        cudaFuncAttributeMaxDynamicSharedMemorySize, gemm_smem);
    cudaFuncSetAttribute(scan_kernel,
        cudaFuncAttributeMaxDynamicSharedMemorySize, scan_smem);
    cudaFuncSetAttribute(qproj_kernel,
        cudaFuncAttributeMaxDynamicSharedMemorySize, qproj_smem);

    // emb = relu(obs @ W_emb + b_emb)
    gemm8x8<true><<<dim3(TBROWS / 64, 1), 128, gemm_smem>>>(obs, W_emb, b_emb, embys, 128);
    // gi = emb @ Wi + bi
    gemm8x8<false><<<dim3(TBROWS / 64, 3), 128, gemm_smem>>>(embys, Wi, bi, gi, 384);
    // GRU scan (hybrid reg/smem Wh; writes ys over emb buffer)
    scan_kernel<<<BATCH / 4, 384, scan_smem>>>(hidden, gi, dones, Wh, bhn,
                                               hfinal, embys);
    // q = ys @ W_out + b_out
    qproj_kernel<<<TBROWS / 128, 128, qproj_smem>>>(embys, W_out, b_out, q);
}

// round 10
// speedup vs baseline: 1.0500x; 1.0500x over previous
#include <cuda_runtime.h>
#include <cstdint>

#define T_STEPS 512
#define BATCH   512
#define HID     128
#define ACT     18
#define TBROWS  (T_STEPS * BATCH)   // 262144

// Scratch (device globals: allocation is forbidden)
__device__ float g_ys[(size_t)TBROWS * HID];         // emb, then ys (reused)
__device__ float g_gi [(size_t)TBROWS * 3 * HID];    // gi

typedef unsigned long long u64;

__device__ __forceinline__ u64 pk2(float x) {
    u64 d; asm("mov.b64 %0, {%1,%1};" : "=l"(d) : "f"(x)); return d;
}
__device__ __forceinline__ u64 pk2two(float a, float b) {
    u64 d; asm("mov.b64 %0, {%1,%2};" : "=l"(d) : "f"(a), "f"(b)); return d;
}
__device__ __forceinline__ void fma2(u64 &c, u64 a, u64 b) {
    asm("fma.rn.f32x2 %0, %1, %2, %3;" : "=l"(c) : "l"(a), "l"(b), "l"(c));
}
__device__ __forceinline__ float2 unpk(u64 v) {
    float2 f; asm("mov.b64 {%0,%1}, %2;" : "=f"(f.x), "=f"(f.y) : "l"(v)); return f;
}
__device__ __forceinline__ void cp_async16(uint32_t dst, const void* src) {
    asm volatile("cp.async.ca.shared.global [%0], [%1], 16;" :: "r"(dst), "l"(src));
}

// ---------------------------------------------------------------------------
// GEMM: C[M,N] = act(A[M,128] @ W[128,N] + bias[N]).
// CTA tile 64x128, 128 threads, thread tile 8x8, f32x2 accumulators.
// ---------------------------------------------------------------------------
template<bool RELU>
__global__ __launch_bounds__(128, 2) void gemm8x8(
    const float* __restrict__ A, const float* __restrict__ W,
    const float* __restrict__ bias, float* __restrict__ C, int N)
{
    extern __shared__ float sm[];
    float* As = sm;             // [64][132]
    float* Bs = sm + 64 * 132;  // [128][128]

    const int m0  = blockIdx.x * 64;
    const int n0  = blockIdx.y * 128;
    const int tid = threadIdx.x;

    for (int i = tid; i < 2048; i += 128) {
        int m = i >> 5, kv = (i & 31) << 2;
        *(float4*)(As + m * 132 + kv) =
            *(const float4*)(A + (size_t)(m0 + m) * 128 + kv);
    }
    for (int i = tid; i < 4096; i += 128) {
        int k = i >> 5, nv = (i & 31) << 2;
        *(float4*)(Bs + k * 128 + nv) =
            *(const float4*)(W + (size_t)k * N + n0 + nv);
    }
    __syncthreads();

    const int tx = tid & 15;
    const int ty = tid >> 4;

    u64 acc[8][4];
    #pragma unroll
    for (int r = 0; r < 8; ++r)
        #pragma unroll
        for (int c = 0; c < 4; ++c) acc[r][c] = 0ull;

    const float* ap = As + ty * 8 * 132;
    const u64*   bp = (const u64*)Bs + tx * 4;   // row stride 64 u64

    #pragma unroll
    for (int k4 = 0; k4 < 128; k4 += 4) {
        float4 av[8];
        #pragma unroll
        for (int r = 0; r < 8; ++r)
            av[r] = *(const float4*)(ap + r * 132 + k4);
        #pragma unroll
        for (int kk = 0; kk < 4; ++kk) {
            ulonglong2 b01 = *(const ulonglong2*)(bp + (size_t)(k4 + kk) * 64);
            ulonglong2 b23 = *(const ulonglong2*)(bp + (size_t)(k4 + kk) * 64 + 2);
            #pragma unroll
            for (int r = 0; r < 8; ++r) {
                u64 ad = pk2(((const float*)&av[r])[kk]);
                fma2(acc[r][0], ad, b01.x);
                fma2(acc[r][1], ad, b01.y);
                fma2(acc[r][2], ad, b23.x);
                fma2(acc[r][3], ad, b23.y);
            }
        }
    }

    float bb[8];
    {
        float4 b0 = *(const float4*)(bias + n0 + tx * 8);
        float4 b1 = *(const float4*)(bias + n0 + tx * 8 + 4);
        bb[0]=b0.x; bb[1]=b0.y; bb[2]=b0.z; bb[3]=b0.w;
        bb[4]=b1.x; bb[5]=b1.y; bb[6]=b1.z; bb[7]=b1.w;
    }
    #pragma unroll
    for (int r = 0; r < 8; ++r) {
        float2 f0 = unpk(acc[r][0]), f1 = unpk(acc[r][1]);
        float2 f2 = unpk(acc[r][2]), f3 = unpk(acc[r][3]);
        float v[8] = { f0.x, f0.y, f1.x, f1.y, f2.x, f2.y, f3.x, f3.y };
        #pragma unroll
        for (int j = 0; j < 8; ++j) {
            v[j] += bb[j];
            if (RELU) v[j] = fmaxf(v[j], 0.0f);
        }
        float* cp = C + (size_t)(m0 + ty * 8 + r) * N + n0 + tx * 8;
        *(float4*)(cp)     = make_float4(v[0], v[1], v[2], v[3]);
        *(float4*)(cp + 4) = make_float4(v[4], v[5], v[6], v[7]);
    }
}

// ---------------------------------------------------------------------------
// Scan: 128 CTAs x 768 threads (24 warps, 6/SMSP), 4 batch rows per CTA.
// k-SPLIT: thread (half, col) owns Wh[half*64 .. half*64+63][col] in regs
// (w[64] -> fits 85-reg cap). Partials combined inside the gate phase; still
// 2 barriers/step. Gates: exactly 1 item per thread (tid < 512).
// ---------------------------------------------------------------------------
__device__ __forceinline__ float sigf(float x) {
    return __fdividef(1.0f, 1.0f + __expf(-x));
}
__device__ __forceinline__ float tanhfast(float x) {
    return __fdividef(2.0f, 1.0f + __expf(-2.0f * x)) - 1.0f;
}

__global__ __launch_bounds__(768, 1) void scan_kernel(
    const float* __restrict__ hidden, const float* __restrict__ gi_all,
    const int* __restrict__ dones,
    const float* __restrict__ Wh, const float* __restrict__ bhn,
    float* __restrict__ hfinal, float* __restrict__ ys)
{
    __shared__ float4 h4_s[128];        // h of 4 rows per hidden dim
    __shared__ u64    p01_s[2][384];    // partial gh rows 0,1 per k-half
    __shared__ u64    p23_s[2][384];    // partial gh rows 2,3 per k-half
    __shared__ float  bhn_s[128];
    __shared__ float  maskf_s[T_STEPS * 4];
    __shared__ float  gi_s[2][1536];

    const int tid  = threadIdx.x;            // 0..767
    const int half = (tid >= 384) ? 1 : 0;   // k-half
    const int col  = tid - half * 384;       // Wh column 0..383
    const int b0   = blockIdx.x * 4;

    const uint32_t gi_smem = (uint32_t)__cvta_generic_to_shared(&gi_s[0][0])
                             + (uint32_t)tid * 16u;
    const float* gi_src = gi_all + (size_t)b0 * 384 + tid * 4;

    // Kick off gi for t=0 (producers: tid < 384)
    if (tid < 384) {
        cp_async16(gi_smem, gi_src);
        asm volatile("cp.async.commit_group;");
    }

    // Wh half-column -> registers (coalesced LDG: col consecutive per warp)
    float w[64];
    #pragma unroll
    for (int k = 0; k < 64; ++k)
        w[k] = Wh[(size_t)(half * 64 + k) * 384 + col];

    if (tid < 128) bhn_s[tid] = bhn[tid];
    for (int i = tid; i < T_STEPS * 4; i += 768) {
        int t = i >> 2, r = i & 3;
        maskf_s[i] = dones[t * BATCH + b0 + r] ? 0.0f : 1.0f;
    }
    if (tid < 512) {
        int r = tid >> 7, i = tid & 127;
        ((float*)&h4_s[i])[r] = hidden[(size_t)(b0 + r) * 128 + i];
    }
    __syncthreads();

    const int rr0 = tid >> 7;     // gate row (valid for tid < 512)
    const int i0  = tid & 127;    // gate hidden index
    const float4* hp = h4_s + half * 64;

    for (int t = 0; t < T_STEPS; ++t) {
        // issue cp.async for t+1 (producers only; lands during the matvec)
        if (tid < 384 && t + 1 < T_STEPS) {
            cp_async16(gi_smem + (((t + 1) & 1) ? 6144u : 0u),
                       gi_src + (size_t)(t + 1) * (BATCH * 384));
            asm volatile("cp.async.commit_group;");
        }

        // partial matvec over own k-half: 64 k
        u64 a01 = 0ull, a23 = 0ull;
        #pragma unroll
        for (int k = 0; k < 64; ++k) {
            ulonglong2 hv = *(const ulonglong2*)&hp[k];
            u64 wd = pk2(w[k]);
            fma2(a01, hv.x, wd);
            fma2(a23, hv.y, wd);
        }
        p01_s[half][col] = a01;
        p23_s[half][col] = a23;

        if (tid < 384) {
            if (t + 1 < T_STEPS) {
                asm volatile("cp.async.wait_group 1;");
            } else {
                asm volatile("cp.async.wait_group 0;");
            }
        }
        __syncthreads();   // (A) partials + gi[t] visible; h4 reads done

        // gates: one item per thread (tid < 512)
        if (tid < 512) {
            const float mk = maskf_s[t * 4 + rr0];
            const int sub = rr0 & 1;
            const float* q0 = (rr0 < 2) ? (const float*)p01_s[0]
                                        : (const float*)p23_s[0];
            const float* q1 = (rr0 < 2) ? (const float*)p01_s[1]
                                        : (const float*)p23_s[1];
            float ghr = q0[2 * i0 + sub]         + q1[2 * i0 + sub];
            float ghz = q0[2 * (128 + i0) + sub] + q1[2 * (128 + i0) + sub];
            float ghn = q0[2 * (256 + i0) + sub] + q1[2 * (256 + i0) + sub];

            const float* gb = gi_s[t & 1] + rr0 * 384;
            float rg = sigf(gb[i0] + mk * ghr);
            float zg = sigf(gb[128 + i0] + mk * ghz);
            float nv = tanhfast(gb[256 + i0] + rg * (mk * ghn + bhn_s[i0]));
            float* hps = ((float*)&h4_s[i0]) + rr0;
            float hn = (1.0f - zg) * nv + zg * (*hps * mk);
            *hps = hn;
            ys[((size_t)t * BATCH + b0 + rr0) * 128 + i0] = hn;
        }
        __syncthreads();   // (B) h4 updated before next matvec
    }

    if (tid < 512) {
        int r = tid >> 7, i = tid & 127;
        hfinal[(size_t)(b0 + r) * 128 + i] = ((float*)&h4_s[i])[r];
    }
}

// ---------------------------------------------------------------------------
// q projection: q[M,18] = ys[M,128] @ W_out[128,18] + b_out.
// 128 rows/CTA, 128 threads (1 row/thread), 2 CTAs/SM.
// ---------------------------------------------------------------------------
__global__ __launch_bounds__(128, 2) void qproj_kernel(
    const float* __restrict__ ys, const float* __restrict__ Wo,
    const float* __restrict__ bo, float* __restrict__ q)
{
    extern __shared__ float sm[];
    float* As   = sm;                 // [128][129]
    float* Wo_s = sm + 128 * 129;     // [128][20]
    float* bo_s = Wo_s + 128 * 20;    // [18]

    const int tid = threadIdx.x;
    const size_t m0 = (size_t)blockIdx.x * 128;

    for (int i = tid; i < 4096; i += 128) {
        int m = i >> 5, kv = (i & 31) << 2;
        float4 v = *(const float4*)(ys + (m0 + m) * 128 + kv);
        float* d = As + m * 129 + kv;
        d[0] = v.x; d[1] = v.y; d[2] = v.z; d[3] = v.w;
    }
    for (int i = tid; i < 128 * 18; i += 128)
        Wo_s[(i / 18) * 20 + (i % 18)] = Wo[i];
    if (tid < 18) bo_s[tid] = bo[tid];
    __syncthreads();

    u64 acc[9];
    #pragma unroll
    for (int p = 0; p < 9; ++p) acc[p] = pk2two(bo_s[2 * p], bo_s[2 * p + 1]);

    const float* ap = As + tid * 129;
    #pragma unroll 4
    for (int k = 0; k < 128; ++k) {
        u64 hd = pk2(ap[k]);
        const u64* wrow = (const u64*)(Wo_s + k * 20);
        #pragma unroll
        for (int p = 0; p < 9; ++p) fma2(acc[p], hd, wrow[p]);
    }

    float* qp = q + (m0 + tid) * ACT;
    #pragma unroll
    for (int p = 0; p < 9; ++p) {
        float2 f = unpk(acc[p]);
        *(float2*)(qp + 2 * p) = f;
    }
}

// ---------------------------------------------------------------------------
extern "C" void kernel_launch(void* const* d_in, const int* in_sizes, int n_in,
                              void* d_out, int out_size)
{
    const float* hidden = (const float*)d_in[0];
    const float* obs    = (const float*)d_in[1];
    const int*   dones  = (const int*)d_in[2];
    const float* W_emb  = (const float*)d_in[3];
    const float* b_emb  = (const float*)d_in[4];
    const float* Wi     = (const float*)d_in[5];
    const float* bi     = (const float*)d_in[6];
    const float* Wh     = (const float*)d_in[7];
    const float* bhn    = (const float*)d_in[8];
    const float* W_out  = (const float*)d_in[9];
    const float* b_out  = (const float*)d_in[10];

    float* out    = (float*)d_out;
    float* hfinal = out;                        // [512, 128]
    float* q      = out + (size_t)BATCH * HID;  // [512, 512, 18]

    void *p_ys, *p_gi;
    cudaGetSymbolAddress(&p_ys, g_ys);
    cudaGetSymbolAddress(&p_gi, g_gi);
    float* embys = (float*)p_ys;   // emb, later ys
    float* gi    = (float*)p_gi;

    const int gemm_smem  = (64 * 132 + 128 * 128) * 4;       // 99328 B
    const int qproj_smem = (128 * 129 + 128 * 20 + 18) * 4;  // 76360 B
    cudaFuncSetAttribute(gemm8x8<true>,
        cudaFuncAttributeMaxDynamicSharedMemorySize, gemm_smem);
    cudaFuncSetAttribute(gemm8x8<false>,
        cudaFuncAttributeMaxDynamicSharedMemorySize, gemm_smem);
    cudaFuncSetAttribute(qproj_kernel,
        cudaFuncAttributeMaxDynamicSharedMemorySize, qproj_smem);

    // emb = relu(obs @ W_emb + b_emb)
    gemm8x8<true><<<dim3(TBROWS / 64, 1), 128, gemm_smem>>>(obs, W_emb, b_emb, embys, 128);
    // gi = emb @ Wi + bi
    gemm8x8<false><<<dim3(TBROWS / 64, 3), 128, gemm_smem>>>(embys, Wi, bi, gi, 384);
    // GRU scan (k-split, 768 threads; writes ys over emb buffer)
    scan_kernel<<<BATCH / 4, 768>>>(hidden, gi, dones, Wh, bhn, hfinal, embys);
    // q = ys @ W_out + b_out
    qproj_kernel<<<TBROWS / 128, 128, qproj_smem>>>(embys, W_out, b_out, q);
}

// round 11
// speedup vs baseline: 1.7330x; 1.6506x over previous
#include <cuda_runtime.h>
#include <cstdint>

#define T_STEPS 512
#define BATCH   512
#define HID     128
#define ACT     18
#define TBROWS  (T_STEPS * BATCH)   // 262144

// Scratch (device globals: allocation is forbidden)
__device__ float g_ys[(size_t)TBROWS * HID];         // emb, then ys (reused)
__device__ float g_gi [(size_t)TBROWS * 3 * HID];    // gi

typedef unsigned long long u64;

__device__ __forceinline__ u64 pk2(float x) {
    u64 d; asm("mov.b64 %0, {%1,%1};" : "=l"(d) : "f"(x)); return d;
}
__device__ __forceinline__ u64 pk2two(float a, float b) {
    u64 d; asm("mov.b64 %0, {%1,%2};" : "=l"(d) : "f"(a), "f"(b)); return d;
}
__device__ __forceinline__ void fma2(u64 &c, u64 a, u64 b) {
    asm("fma.rn.f32x2 %0, %1, %2, %3;" : "=l"(c) : "l"(a), "l"(b), "l"(c));
}
__device__ __forceinline__ u64 mul2(u64 a, u64 b) {
    u64 d; asm("mul.rn.f32x2 %0, %1, %2;" : "=l"(d) : "l"(a), "l"(b)); return d;
}
__device__ __forceinline__ float2 unpk(u64 v) {
    float2 f; asm("mov.b64 {%0,%1}, %2;" : "=f"(f.x), "=f"(f.y) : "l"(v)); return f;
}
__device__ __forceinline__ void cp_async16(uint32_t dst, const void* src) {
    asm volatile("cp.async.ca.shared.global [%0], [%1], 16;" :: "r"(dst), "l"(src));
}

// ---------------------------------------------------------------------------
// GEMM: C[M,N] = act(A[M,128] @ W[128,N] + bias[N]).
// CTA tile 64x128, 128 threads, thread tile 8x8, f32x2 accumulators.
// ---------------------------------------------------------------------------
template<bool RELU>
__global__ __launch_bounds__(128, 2) void gemm8x8(
    const float* __restrict__ A, const float* __restrict__ W,
    const float* __restrict__ bias, float* __restrict__ C, int N)
{
    extern __shared__ float sm[];
    float* As = sm;             // [64][132]
    float* Bs = sm + 64 * 132;  // [128][128]

    const int m0  = blockIdx.x * 64;
    const int n0  = blockIdx.y * 128;
    const int tid = threadIdx.x;

    for (int i = tid; i < 2048; i += 128) {
        int m = i >> 5, kv = (i & 31) << 2;
        *(float4*)(As + m * 132 + kv) =
            *(const float4*)(A + (size_t)(m0 + m) * 128 + kv);
    }
    for (int i = tid; i < 4096; i += 128) {
        int k = i >> 5, nv = (i & 31) << 2;
        *(float4*)(Bs + k * 128 + nv) =
            *(const float4*)(W + (size_t)k * N + n0 + nv);
    }
    __syncthreads();

    const int tx = tid & 15;
    const int ty = tid >> 4;

    u64 acc[8][4];
    #pragma unroll
    for (int r = 0; r < 8; ++r)
        #pragma unroll
        for (int c = 0; c < 4; ++c) acc[r][c] = 0ull;

    const float* ap = As + ty * 8 * 132;
    const u64*   bp = (const u64*)Bs + tx * 4;   // row stride 64 u64

    #pragma unroll
    for (int k4 = 0; k4 < 128; k4 += 4) {
        float4 av[8];
        #pragma unroll
        for (int r = 0; r < 8; ++r)
            av[r] = *(const float4*)(ap + r * 132 + k4);
        #pragma unroll
        for (int kk = 0; kk < 4; ++kk) {
            ulonglong2 b01 = *(const ulonglong2*)(bp + (size_t)(k4 + kk) * 64);
            ulonglong2 b23 = *(const ulonglong2*)(bp + (size_t)(k4 + kk) * 64 + 2);
            #pragma unroll
            for (int r = 0; r < 8; ++r) {
                u64 ad = pk2(((const float*)&av[r])[kk]);
                fma2(acc[r][0], ad, b01.x);
                fma2(acc[r][1], ad, b01.y);
                fma2(acc[r][2], ad, b23.x);
                fma2(acc[r][3], ad, b23.y);
            }
        }
    }

    float bb[8];
    {
        float4 b0 = *(const float4*)(bias + n0 + tx * 8);
        float4 b1 = *(const float4*)(bias + n0 + tx * 8 + 4);
        bb[0]=b0.x; bb[1]=b0.y; bb[2]=b0.z; bb[3]=b0.w;
        bb[4]=b1.x; bb[5]=b1.y; bb[6]=b1.z; bb[7]=b1.w;
    }
    #pragma unroll
    for (int r = 0; r < 8; ++r) {
        float2 f0 = unpk(acc[r][0]), f1 = unpk(acc[r][1]);
        float2 f2 = unpk(acc[r][2]), f3 = unpk(acc[r][3]);
        float v[8] = { f0.x, f0.y, f1.x, f1.y, f2.x, f2.y, f3.x, f3.y };
        #pragma unroll
        for (int j = 0; j < 8; ++j) {
            v[j] += bb[j];
            if (RELU) v[j] = fmaxf(v[j], 0.0f);
        }
        float* cp = C + (size_t)(m0 + ty * 8 + r) * N + n0 + tx * 8;
        *(float4*)(cp)     = make_float4(v[0], v[1], v[2], v[3]);
        *(float4*)(cp + 4) = make_float4(v[4], v[5], v[6], v[7]);
    }
}

// ---------------------------------------------------------------------------
// Scan: 128 CTAs x 384 threads, 4 batch rows per CTA (R5 structure).
// NEW: gate phase processes ROW-PAIRS in packed f32x2 (gh partials are
// already {row0,row1}/{row2,row3} u64s). sigmoid/tanh stay exact scalar.
// ---------------------------------------------------------------------------
__device__ __forceinline__ float sigf(float x) {
    return __fdividef(1.0f, 1.0f + __expf(-x));
}
__device__ __forceinline__ float tanhfast(float x) {
    return __fdividef(2.0f, 1.0f + __expf(-2.0f * x)) - 1.0f;
}

__global__ __launch_bounds__(384, 1) void scan_kernel(
    const float* __restrict__ hidden, const float* __restrict__ gi_all,
    const int* __restrict__ dones,
    const float* __restrict__ Wh, const float* __restrict__ bhn,
    float* __restrict__ hfinal, float* __restrict__ ys)
{
    __shared__ float4 h4_s[128];        // h of 4 rows per hidden dim
    __shared__ u64    gh01_s[384];      // gh rows {0,1} packed per column
    __shared__ u64    gh23_s[384];      // gh rows {2,3} packed per column
    __shared__ u64    bhn2_s[128];      // bhn packed {b,b}
    __shared__ u64    maskp_s[T_STEPS * 2];  // packed masks per (t, pair)
    __shared__ float  gi_s[2][1536];    // double-buffered gi slice

    const int tid = threadIdx.x;
    const int b0  = blockIdx.x * 4;

    const uint32_t gi_smem = (uint32_t)__cvta_generic_to_shared(&gi_s[0][0])
                             + (uint32_t)tid * 16u;
    const float* gi_src = gi_all + (size_t)b0 * 384 + tid * 4;

    // Kick off gi for t=0 immediately
    cp_async16(gi_smem, gi_src);
    asm volatile("cp.async.commit_group;");

    // Wh column tid -> registers (coalesced LDG across threads)
    float w[128];
    #pragma unroll
    for (int k = 0; k < 128; ++k)
        w[k] = Wh[(size_t)k * 384 + tid];

    if (tid < 128) bhn2_s[tid] = pk2(bhn[tid]);
    for (int i = tid; i < T_STEPS * 2; i += 384) {
        int t = i >> 1, p = i & 1;
        float m0_ = dones[t * BATCH + b0 + 2 * p]     ? 0.0f : 1.0f;
        float m1_ = dones[t * BATCH + b0 + 2 * p + 1] ? 0.0f : 1.0f;
        maskp_s[i] = pk2two(m0_, m1_);
    }
    for (int idx = tid; idx < 512; idx += 384) {
        int r = idx >> 7, i = idx & 127;
        ((float*)&h4_s[i])[r] = hidden[(size_t)(b0 + r) * 128 + i];
    }
    __syncthreads();

    const u64 NEG1 = pk2two(-1.0f, -1.0f);

    for (int t = 0; t < T_STEPS; ++t) {
        // issue cp.async for t+1 (lands during the matvec)
        if (t + 1 < T_STEPS) {
            cp_async16(gi_smem + (((t + 1) & 1) ? 6144u : 0u),
                       gi_src + (size_t)(t + 1) * (BATCH * 384));
            asm volatile("cp.async.commit_group;");
        }

        // matvec: gh[:, tid] = h4 . w  (w in registers, h4 broadcast LDS)
        u64 a01 = 0ull, a23 = 0ull;
        #pragma unroll
        for (int k = 0; k < 128; ++k) {
            ulonglong2 hv = *(const ulonglong2*)&h4_s[k];
            u64 wd = pk2(w[k]);
            fma2(a01, hv.x, wd);
            fma2(a23, hv.y, wd);
        }
        gh01_s[tid] = a01;
        gh23_s[tid] = a23;

        if (t + 1 < T_STEPS) {
            asm volatile("cp.async.wait_group 1;");   // gi[t] landed
        } else {
            asm volatile("cp.async.wait_group 0;");
        }
        __syncthreads();   // (A) gh + gi[t] visible; matvec reads of h4 done

        // gates: 256 row-pair items, one per thread (tid < 256), packed f32x2
        if (tid < 256) {
            const int p = tid >> 7;       // 0 -> rows {0,1}, 1 -> rows {2,3}
            const int i = tid & 127;
            const u64* ghb = p ? gh23_s : gh01_s;
            const u64 mkp = maskp_s[t * 2 + p];

            u64 ghr = ghb[i];
            u64 ghz = ghb[128 + i];
            u64 ghn = ghb[256 + i];

            const float* gb0 = gi_s[t & 1] + (2 * p) * 384;
            const float* gb1 = gb0 + 384;
            u64 xr = pk2two(gb0[i],       gb1[i]);        fma2(xr, ghr, mkp);
            u64 xz = pk2two(gb0[128 + i], gb1[128 + i]);  fma2(xz, ghz, mkp);
            u64 gn = pk2two(gb0[256 + i], gb1[256 + i]);
            u64 t0 = bhn2_s[i];                           fma2(t0, ghn, mkp);

            float2 fr = unpk(xr);
            float2 fz = unpk(xz);
            u64 rp = pk2two(sigf(fr.x), sigf(fr.y));
            u64 zp = pk2two(sigf(fz.x), sigf(fz.y));

            u64 xn = gn; fma2(xn, rp, t0);
            float2 fn = unpk(xn);
            u64 np = pk2two(tanhfast(fn.x), tanhfast(fn.y));

            u64* hp = (u64*)(((char*)&h4_s[i]) + p * 8);
            u64 hm = mul2(*hp, mkp);          // h' = h * mask
            u64 d  = hm; fma2(d, np, NEG1);   // d  = h' - n
            u64 hn = np; fma2(hn, zp, d);     // hn = z*d + n
            *hp = hn;

            float2 fh = unpk(hn);
            float* yp = ys + ((size_t)t * BATCH + b0 + 2 * p) * 128 + i;
            yp[0]   = fh.x;
            yp[128] = fh.y;
        }
        __syncthreads();   // (B) h4 updated before next matvec
    }

    for (int idx = tid; idx < 512; idx += 384) {
        int r = idx >> 7, i = idx & 127;
        hfinal[(size_t)(b0 + r) * 128 + i] = ((float*)&h4_s[i])[r];
    }
}

// ---------------------------------------------------------------------------
// q projection: q[M,18] = ys[M,128] @ W_out[128,18] + b_out.
// 128 rows/CTA, 128 threads (1 row/thread), 2 CTAs/SM. (clock canary — R4)
// ---------------------------------------------------------------------------
__global__ __launch_bounds__(128, 2) void qproj_kernel(
    const float* __restrict__ ys, const float* __restrict__ Wo,
    const float* __restrict__ bo, float* __restrict__ q)
{
    extern __shared__ float sm[];
    float* As   = sm;                 // [128][129]
    float* Wo_s = sm + 128 * 129;     // [128][20]
    float* bo_s = Wo_s + 128 * 20;    // [18]

    const int tid = threadIdx.x;
    const size_t m0 = (size_t)blockIdx.x * 128;

    for (int i = tid; i < 4096; i += 128) {
        int m = i >> 5, kv = (i & 31) << 2;
        float4 v = *(const float4*)(ys + (m0 + m) * 128 + kv);
        float* d = As + m * 129 + kv;
        d[0] = v.x; d[1] = v.y; d[2] = v.z; d[3] = v.w;
    }
    for (int i = tid; i < 128 * 18; i += 128)
        Wo_s[(i / 18) * 20 + (i % 18)] = Wo[i];
    if (tid < 18) bo_s[tid] = bo[tid];
    __syncthreads();

    u64 acc[9];
    #pragma unroll
    for (int p = 0; p < 9; ++p) acc[p] = pk2two(bo_s[2 * p], bo_s[2 * p + 1]);

    const float* ap = As + tid * 129;
    #pragma unroll 4
    for (int k = 0; k < 128; ++k) {
        u64 hd = pk2(ap[k]);
        const u64* wrow = (const u64*)(Wo_s + k * 20);
        #pragma unroll
        for (int p = 0; p < 9; ++p) fma2(acc[p], hd, wrow[p]);
    }

    float* qp = q + (m0 + tid) * ACT;
    #pragma unroll
    for (int p = 0; p < 9; ++p) {
        float2 f = unpk(acc[p]);
        *(float2*)(qp + 2 * p) = f;
    }
}

// ---------------------------------------------------------------------------
extern "C" void kernel_launch(void* const* d_in, const int* in_sizes, int n_in,
                              void* d_out, int out_size)
{
    const float* hidden = (const float*)d_in[0];
    const float* obs    = (const float*)d_in[1];
    const int*   dones  = (const int*)d_in[2];
    const float* W_emb  = (const float*)d_in[3];
    const float* b_emb  = (const float*)d_in[4];
    const float* Wi     = (const float*)d_in[5];
    const float* bi     = (const float*)d_in[6];
    const float* Wh     = (const float*)d_in[7];
    const float* bhn    = (const float*)d_in[8];
    const float* W_out  = (const float*)d_in[9];
    const float* b_out  = (const float*)d_in[10];

    float* out    = (float*)d_out;
    float* hfinal = out;                        // [512, 128]
    float* q      = out + (size_t)BATCH * HID;  // [512, 512, 18]

    void *p_ys, *p_gi;
    cudaGetSymbolAddress(&p_ys, g_ys);
    cudaGetSymbolAddress(&p_gi, g_gi);
    float* embys = (float*)p_ys;   // emb, later ys
    float* gi    = (float*)p_gi;

    const int gemm_smem  = (64 * 132 + 128 * 128) * 4;       // 99328 B
    const int qproj_smem = (128 * 129 + 128 * 20 + 18) * 4;  // 76360 B
    cudaFuncSetAttribute(gemm8x8<true>,
        cudaFuncAttributeMaxDynamicSharedMemorySize, gemm_smem);
    cudaFuncSetAttribute(gemm8x8<false>,
        cudaFuncAttributeMaxDynamicSharedMemorySize, gemm_smem);
    cudaFuncSetAttribute(qproj_kernel,
        cudaFuncAttributeMaxDynamicSharedMemorySize, qproj_smem);

    // emb = relu(obs @ W_emb + b_emb)
    gemm8x8<true><<<dim3(TBROWS / 64, 1), 128, gemm_smem>>>(obs, W_emb, b_emb, embys, 128);
    // gi = emb @ Wi + bi
    gemm8x8<false><<<dim3(TBROWS / 64, 3), 128, gemm_smem>>>(embys, Wi, bi, gi, 384);
    // GRU scan (R5 shell + packed-pair gates; writes ys over emb buffer)
    scan_kernel<<<BATCH / 4, 384>>>(hidden, gi, dones, Wh, bhn, hfinal, embys);
    // q = ys @ W_out + b_out
    qproj_kernel<<<TBROWS / 128, 128, qproj_smem>>>(embys, W_out, b_out, q);
}